// round 6
// baseline (speedup 1.0000x reference)
#include <cuda_runtime.h>

// GIN model, fully restructured:
//   P1 = x @ W11x                                  (GEMM, K=64)
//   L1 fused: gather(P1) -> smem; h = relu(agg@W12 + (deg+1)b12) (smem only);
//             P2 = h @ W21x                         -> global
//   L2 fused: gather(P2) -> smem; out = agg@W22 + (deg+1)b22
// CSR (by dst) built once, shared by both layers. No atomics in hot path.

#define HD 128
#define MAX_N 100000
#define MAX_E 1600000
#define AG_LD 132   // agg smem row stride (floats): 16B-aligned, bank-safe

__device__ float g_P[(long long)MAX_N * HD];    // P1 table
__device__ float g_h[(long long)MAX_N * HD];    // P2 table
__device__ int    g_cnt[MAX_N];
__device__ int    g_fill[MAX_N];
__device__ int    g_rowptr[MAX_N + 1];
__device__ int    g_bsum[128];
__device__ int    g_boff[128];
__device__ int    g_src[MAX_E];
__device__ float2 g_eas[MAX_E];

typedef unsigned long long ull;

__device__ __forceinline__ ull pk2(float x, float y) {
    ull r; asm("mov.b64 %0, {%1, %2};" : "=l"(r) : "f"(x), "f"(y)); return r;
}
__device__ __forceinline__ void upk2(ull v, float& x, float& y) {
    asm("mov.b64 {%0, %1}, %2;" : "=f"(x), "=f"(y) : "l"(v));
}
__device__ __forceinline__ ull fma2(ull a, ull b, ull c) {
    ull d; asm("fma.rn.f32x2 %0, %1, %2, %3;" : "=l"(d) : "l"(a), "l"(b), "l"(c));
    return d;
}
__device__ __forceinline__ void cp16(void* smem_dst, const void* gsrc, int src_bytes) {
    unsigned s = (unsigned)__cvta_generic_to_shared(smem_dst);
    asm volatile("cp.async.ca.shared.global [%0], [%1], 16, %2;"
                 :: "r"(s), "l"(gsrc), "r"(src_bytes));
}
__device__ __forceinline__ void cp_commit() { asm volatile("cp.async.commit_group;"); }
template <int NN>
__device__ __forceinline__ void cp_wait() {
    asm volatile("cp.async.wait_group %0;" :: "n"(NN));
}

// ============================== CSR build ==================================
__global__ void zero_cnt_kernel(int* __restrict__ cnt, int* __restrict__ fill, int N) {
    int i = blockIdx.x * blockDim.x + threadIdx.x;
    if (i < N) { cnt[i] = 0; fill[i] = 0; }
}

__global__ void count_kernel(const int* __restrict__ ei, int* __restrict__ cnt, int E) {
    int e = blockIdx.x * blockDim.x + threadIdx.x;
    if (e < E) atomicAdd(&cnt[ei[E + e]], 1);
}

__global__ void scan_reduce_kernel(const int* __restrict__ cnt, int* __restrict__ bsum, int N) {
    __shared__ int sh[256];
    int base = blockIdx.x * 1024;
    int s = 0;
    for (int i = threadIdx.x; i < 1024; i += 256) {
        int idx = base + i;
        if (idx < N) s += cnt[idx];
    }
    sh[threadIdx.x] = s; __syncthreads();
    for (int off = 128; off > 0; off >>= 1) {
        if (threadIdx.x < off) sh[threadIdx.x] += sh[threadIdx.x + off];
        __syncthreads();
    }
    if (threadIdx.x == 0) bsum[blockIdx.x] = sh[0];
}

__global__ void scan_bsums_kernel(const int* __restrict__ bsum, int* __restrict__ boff,
                                  int nb, int* __restrict__ rowptr, int N, int E) {
    if (threadIdx.x == 0) {
        int run = 0;
        for (int i = 0; i < nb; ++i) { boff[i] = run; run += bsum[i]; }
        rowptr[N] = E;
    }
}

__global__ void scan_block_kernel(const int* __restrict__ cnt, const int* __restrict__ boff,
                                  int* __restrict__ rowptr, int N) {
    __shared__ int sh[1024];
    const int tid = threadIdx.x;
    const int idx = blockIdx.x * 1024 + tid;
    int v = (idx < N) ? cnt[idx] : 0;
    sh[tid] = v; __syncthreads();
#pragma unroll
    for (int off = 1; off < 1024; off <<= 1) {
        int t = (tid >= off) ? sh[tid - off] : 0;
        __syncthreads();
        sh[tid] += t;
        __syncthreads();
    }
    if (idx < N) rowptr[idx] = boff[blockIdx.x] + sh[tid] - v;
}

__global__ void fill_kernel(const int* __restrict__ ei, const float* __restrict__ ea,
                            const int* __restrict__ rowptr, int* __restrict__ fill,
                            int* __restrict__ srcs, float2* __restrict__ eas, int E) {
    int e = blockIdx.x * blockDim.x + threadIdx.x;
    if (e >= E) return;
    int dst = ei[E + e];
    int slot = rowptr[dst] + atomicAdd(&fill[dst], 1);
    srcs[slot] = ei[e];
    eas[slot] = make_float2(ea[2 * e], ea[2 * e + 1]);
}

// ======================== plain GEMM (layer-1 P) ===========================
// C[N,128] = A[N,K] @ W[K,128]
#define AS_LD 36

__global__ __launch_bounds__(256, 2)
void gemm_kernel(const float* __restrict__ A, const float* __restrict__ W,
                 float* __restrict__ C, int N, int K)
{
    __shared__ float Ws[2][32][128];
    __shared__ float As[2][128][AS_LD];

    const int tid = threadIdx.x;
    const int tx = tid & 15;
    const int ty = tid >> 4;
    const int row0 = blockIdx.x * 128;

    const int wk = tid >> 5;
    const int wc = (tid & 31) * 4;
    const int ar = tid >> 1;
    const int ak = (tid & 1) * 16;

    ull acc[8][4];
#pragma unroll
    for (int r = 0; r < 8; ++r)
#pragma unroll
        for (int p = 0; p < 4; ++p) acc[r][p] = 0ULL;

    const int nt = K >> 5;

    auto load_tile = [&](int buf, int k0) {
#pragma unroll
        for (int j = 0; j < 4; ++j) {
            int kk = wk + j * 8;
            cp16(&Ws[buf][kk][wc], &W[(k0 + kk) * 128 + wc], 16);
        }
        int row = row0 + ar;
        int ok = (row < N) ? 16 : 0;
        const float* ap = &A[(long long)row * K + k0 + ak];
        cp16(&As[buf][ar][ak + 0],  ap + 0,  ok);
        cp16(&As[buf][ar][ak + 4],  ap + 4,  ok);
        cp16(&As[buf][ar][ak + 8],  ap + 8,  ok);
        cp16(&As[buf][ar][ak + 12], ap + 12, ok);
    };

    load_tile(0, 0);
    cp_commit();

    for (int t = 0; t < nt; ++t) {
        const int buf = t & 1;
        if (t + 1 < nt) {
            load_tile(buf ^ 1, (t + 1) * 32);
            cp_commit();
            cp_wait<1>();
        } else {
            cp_wait<0>();
        }
        __syncthreads();
#pragma unroll
        for (int k = 0; k < 32; ++k) {
            ulonglong2 wA = *(const ulonglong2*)&Ws[buf][k][tx * 8];
            ulonglong2 wB = *(const ulonglong2*)&Ws[buf][k][tx * 8 + 4];
#pragma unroll
            for (int r = 0; r < 8; ++r) {
                float a = As[buf][ty + 16 * r][k];   // drow=1 within warp: bank-safe
                ull aa = pk2(a, a);
                acc[r][0] = fma2(aa, wA.x, acc[r][0]);
                acc[r][1] = fma2(aa, wA.y, acc[r][1]);
                acc[r][2] = fma2(aa, wB.x, acc[r][2]);
                acc[r][3] = fma2(aa, wB.y, acc[r][3]);
            }
        }
        __syncthreads();
    }

    const int c0 = tx * 8;
#pragma unroll
    for (int r = 0; r < 8; ++r) {
        int row = row0 + ty + 16 * r;
        if (row >= N) continue;
        float v[8];
#pragma unroll
        for (int p = 0; p < 4; ++p) upk2(acc[r][p], v[2 * p], v[2 * p + 1]);
        float4* dst = (float4*)&C[(long long)row * 128 + c0];
        dst[0] = make_float4(v[0], v[1], v[2], v[3]);
        dst[1] = make_float4(v[4], v[5], v[6], v[7]);
    }
}

// ===================== fused layer kernel ==================================
// Per block of 128 nodes:
//  (1) gather: Ag[ln] = relu(Pin[n]+gw0+gw1+gb) + sum_e relu(Pin[src]+ea.gw+gb)
//  (2) GEMM1:  v = Ag @ W2;  t1 = v + (deg+1)*b2; relu if relu2
//  (3) if W3:  h -> Ag (smem);  out = Ag @ W3   (raw)
//      else:   out = t1
__global__ __launch_bounds__(256, 2)
void fused_kernel(const int* __restrict__ rowptr, const int* __restrict__ srcs,
                  const float2* __restrict__ eas, const float* __restrict__ Pin,
                  const float* __restrict__ gw0, const float* __restrict__ gw1,
                  const float* __restrict__ gb,
                  const float* __restrict__ W2, const float* __restrict__ b2,
                  int relu2,
                  const float* __restrict__ W3,
                  float* __restrict__ out, int N)
{
    extern __shared__ float sh[];
    float* Ag = sh;                          // [128][AG_LD]
    float* WsB = sh + 128 * AG_LD;           // [2][32][128]

    const int tid  = threadIdx.x;
    const int lane = tid & 31;
    const int wid  = tid >> 5;
    const int tx   = tid & 15;
    const int ty   = tid >> 4;
    const int row0 = blockIdx.x * 128;

    const int wk = tid >> 5;
    const int wc = (tid & 31) * 4;

    auto loadW = [&](int buf, const float* Wsrc, int k0) {
#pragma unroll
        for (int j = 0; j < 4; ++j) {
            int kk = wk + j * 8;
            cp16(WsB + (buf * 32 + kk) * 128 + wc, Wsrc + (k0 + kk) * 128 + wc, 16);
        }
    };

    // prefetch W2 tile 0; overlaps the gather phase
    loadW(0, W2, 0);
    cp_commit();

    // ------------------ gather into smem tile ------------------
    {
        const int c = lane * 4;
        const float4 wa = *(const float4*)(gw0 + c);
        const float4 wb = *(const float4*)(gw1 + c);
        const float4 bb = *(const float4*)(gb + c);

        for (int ln = wid; ln < 128; ln += 8) {
            int n = row0 + ln;
            float4 acc = make_float4(0.f, 0.f, 0.f, 0.f);
            if (n < N) {
                float4 ps = *(const float4*)(Pin + (long long)n * HD + c);
                acc.x = fmaxf(ps.x + wa.x + wb.x + bb.x, 0.f);
                acc.y = fmaxf(ps.y + wa.y + wb.y + bb.y, 0.f);
                acc.z = fmaxf(ps.z + wa.z + wb.z + bb.z, 0.f);
                acc.w = fmaxf(ps.w + wa.w + wb.w + bb.w, 0.f);

                const int s = rowptr[n];
                const int e = rowptr[n + 1];
                int j = s;
                for (; j + 4 <= e; j += 4) {
                    int s0 = srcs[j], s1 = srcs[j+1], s2 = srcs[j+2], s3 = srcs[j+3];
                    float2 e0 = eas[j], e1 = eas[j+1], e2 = eas[j+2], e3 = eas[j+3];
                    float4 p0 = *(const float4*)(Pin + (long long)s0 * HD + c);
                    float4 p1 = *(const float4*)(Pin + (long long)s1 * HD + c);
                    float4 p2 = *(const float4*)(Pin + (long long)s2 * HD + c);
                    float4 p3 = *(const float4*)(Pin + (long long)s3 * HD + c);
                    acc.x += fmaxf(fmaf(e0.x, wa.x, fmaf(e0.y, wb.x, p0.x + bb.x)), 0.f);
                    acc.y += fmaxf(fmaf(e0.x, wa.y, fmaf(e0.y, wb.y, p0.y + bb.y)), 0.f);
                    acc.z += fmaxf(fmaf(e0.x, wa.z, fmaf(e0.y, wb.z, p0.z + bb.z)), 0.f);
                    acc.w += fmaxf(fmaf(e0.x, wa.w, fmaf(e0.y, wb.w, p0.w + bb.w)), 0.f);
                    acc.x += fmaxf(fmaf(e1.x, wa.x, fmaf(e1.y, wb.x, p1.x + bb.x)), 0.f);
                    acc.y += fmaxf(fmaf(e1.x, wa.y, fmaf(e1.y, wb.y, p1.y + bb.y)), 0.f);
                    acc.z += fmaxf(fmaf(e1.x, wa.z, fmaf(e1.y, wb.z, p1.z + bb.z)), 0.f);
                    acc.w += fmaxf(fmaf(e1.x, wa.w, fmaf(e1.y, wb.w, p1.w + bb.w)), 0.f);
                    acc.x += fmaxf(fmaf(e2.x, wa.x, fmaf(e2.y, wb.x, p2.x + bb.x)), 0.f);
                    acc.y += fmaxf(fmaf(e2.x, wa.y, fmaf(e2.y, wb.y, p2.y + bb.y)), 0.f);
                    acc.z += fmaxf(fmaf(e2.x, wa.z, fmaf(e2.y, wb.z, p2.z + bb.z)), 0.f);
                    acc.w += fmaxf(fmaf(e2.x, wa.w, fmaf(e2.y, wb.w, p2.w + bb.w)), 0.f);
                    acc.x += fmaxf(fmaf(e3.x, wa.x, fmaf(e3.y, wb.x, p3.x + bb.x)), 0.f);
                    acc.y += fmaxf(fmaf(e3.x, wa.y, fmaf(e3.y, wb.y, p3.y + bb.y)), 0.f);
                    acc.z += fmaxf(fmaf(e3.x, wa.z, fmaf(e3.y, wb.z, p3.z + bb.z)), 0.f);
                    acc.w += fmaxf(fmaf(e3.x, wa.w, fmaf(e3.y, wb.w, p3.w + bb.w)), 0.f);
                }
                for (; j < e; ++j) {
                    int sj = srcs[j];
                    float2 ej = eas[j];
                    float4 p = *(const float4*)(Pin + (long long)sj * HD + c);
                    acc.x += fmaxf(fmaf(ej.x, wa.x, fmaf(ej.y, wb.x, p.x + bb.x)), 0.f);
                    acc.y += fmaxf(fmaf(ej.x, wa.y, fmaf(ej.y, wb.y, p.y + bb.y)), 0.f);
                    acc.z += fmaxf(fmaf(ej.x, wa.z, fmaf(ej.y, wb.z, p.z + bb.z)), 0.f);
                    acc.w += fmaxf(fmaf(ej.x, wa.w, fmaf(ej.y, wb.w, p.w + bb.w)), 0.f);
                }
            }
            *(float4*)(Ag + ln * AG_LD + c) = acc;
        }
    }
    __syncthreads();

    // ------------------ GEMM1: Ag @ W2 ------------------
    ull acc[8][4];
#pragma unroll
    for (int r = 0; r < 8; ++r)
#pragma unroll
        for (int p = 0; p < 4; ++p) acc[r][p] = 0ULL;

#pragma unroll 1
    for (int t = 0; t < 4; ++t) {
        const int buf = t & 1;
        if (t + 1 < 4) { loadW(buf ^ 1, W2, (t + 1) * 32); cp_commit(); cp_wait<1>(); }
        else           { cp_wait<0>(); }
        __syncthreads();
        const float* wbase = WsB + buf * 32 * 128 + tx * 8;
#pragma unroll
        for (int k = 0; k < 32; ++k) {
            ulonglong2 wA = *(const ulonglong2*)(wbase + k * 128);
            ulonglong2 wB = *(const ulonglong2*)(wbase + k * 128 + 4);
            const float* abase = Ag + ty * AG_LD + t * 32 + k;
#pragma unroll
            for (int r = 0; r < 8; ++r) {
                float a = abase[r * 16 * AG_LD];
                ull aa = pk2(a, a);
                acc[r][0] = fma2(aa, wA.x, acc[r][0]);
                acc[r][1] = fma2(aa, wA.y, acc[r][1]);
                acc[r][2] = fma2(aa, wB.x, acc[r][2]);
                acc[r][3] = fma2(aa, wB.y, acc[r][3]);
            }
        }
        __syncthreads();
    }

    const int c0 = tx * 8;

    if (W3) {
        // epilogue 1: h = relu(acc + (deg+1)*b2) -> back into Ag (smem only)
        loadW(0, W3, 0);   // prefetch W3 tile 0 (Ws[0] free: last GEMM1 tile used buf 1)
        cp_commit();
#pragma unroll
        for (int r = 0; r < 8; ++r) {
            int ln = ty + 16 * r;
            int row = row0 + ln;
            float v[8];
#pragma unroll
            for (int p = 0; p < 4; ++p) upk2(acc[r][p], v[2 * p], v[2 * p + 1]);
            float mult = 1.0f;
            if (row < N) mult = (float)(rowptr[row + 1] - rowptr[row]) + 1.0f;
#pragma unroll
            for (int j = 0; j < 8; ++j) {
                float h = v[j] + mult * b2[c0 + j];
                if (relu2) h = fmaxf(h, 0.f);
                v[j] = h;
            }
            *(float4*)(Ag + ln * AG_LD + c0)     = make_float4(v[0], v[1], v[2], v[3]);
            *(float4*)(Ag + ln * AG_LD + c0 + 4) = make_float4(v[4], v[5], v[6], v[7]);
        }
        __syncthreads();

        // ------------------ GEMM2: Ag(h) @ W3 -> out ------------------
#pragma unroll
        for (int r = 0; r < 8; ++r)
#pragma unroll
            for (int p = 0; p < 4; ++p) acc[r][p] = 0ULL;

#pragma unroll 1
        for (int t = 0; t < 4; ++t) {
            const int buf = t & 1;
            if (t + 1 < 4) { loadW(buf ^ 1, W3, (t + 1) * 32); cp_commit(); cp_wait<1>(); }
            else           { cp_wait<0>(); }
            __syncthreads();
            const float* wbase = WsB + buf * 32 * 128 + tx * 8;
#pragma unroll
            for (int k = 0; k < 32; ++k) {
                ulonglong2 wA = *(const ulonglong2*)(wbase + k * 128);
                ulonglong2 wB = *(const ulonglong2*)(wbase + k * 128 + 4);
                const float* abase = Ag + ty * AG_LD + t * 32 + k;
#pragma unroll
                for (int r = 0; r < 8; ++r) {
                    float a = abase[r * 16 * AG_LD];
                    ull aa = pk2(a, a);
                    acc[r][0] = fma2(aa, wA.x, acc[r][0]);
                    acc[r][1] = fma2(aa, wA.y, acc[r][1]);
                    acc[r][2] = fma2(aa, wB.x, acc[r][2]);
                    acc[r][3] = fma2(aa, wB.y, acc[r][3]);
                }
            }
            __syncthreads();
        }

#pragma unroll
        for (int r = 0; r < 8; ++r) {
            int row = row0 + ty + 16 * r;
            if (row >= N) continue;
            float v[8];
#pragma unroll
            for (int p = 0; p < 4; ++p) upk2(acc[r][p], v[2 * p], v[2 * p + 1]);
            float4* dst = (float4*)&out[(long long)row * 128 + c0];
            dst[0] = make_float4(v[0], v[1], v[2], v[3]);
            dst[1] = make_float4(v[4], v[5], v[6], v[7]);
        }
    } else {
        // single-GEMM epilogue: out = acc + (deg+1)*b2 (+relu)
#pragma unroll
        for (int r = 0; r < 8; ++r) {
            int row = row0 + ty + 16 * r;
            if (row >= N) continue;
            float v[8];
#pragma unroll
            for (int p = 0; p < 4; ++p) upk2(acc[r][p], v[2 * p], v[2 * p + 1]);
            float mult = (float)(rowptr[row + 1] - rowptr[row]) + 1.0f;
#pragma unroll
            for (int j = 0; j < 8; ++j) {
                float o = v[j] + mult * b2[c0 + j];
                if (relu2) o = fmaxf(o, 0.f);
                v[j] = o;
            }
            float4* dst = (float4*)&out[(long long)row * 128 + c0];
            dst[0] = make_float4(v[0], v[1], v[2], v[3]);
            dst[1] = make_float4(v[4], v[5], v[6], v[7]);
        }
    }
}

// ---------------------------------------------------------------------------
extern "C" void kernel_launch(void* const* d_in, const int* in_sizes, int n_in,
                              void* d_out, int out_size)
{
    const float* x   = (const float*)d_in[0];
    const int*   ei  = (const int*)d_in[1];
    const float* ea  = (const float*)d_in[2];
    const float* W11 = (const float*)d_in[3];
    const float* b11 = (const float*)d_in[4];
    const float* W12 = (const float*)d_in[5];
    const float* b12 = (const float*)d_in[6];
    const float* W21 = (const float*)d_in[7];
    const float* b21 = (const float*)d_in[8];
    const float* W22 = (const float*)d_in[9];
    const float* b22 = (const float*)d_in[10];
    float* out = (float*)d_out;

    const int IN_DIM = 64;
    const int N = in_sizes[0] / IN_DIM;
    const int E = in_sizes[1] / 2;

    float *P1, *P2;
    int *cnt, *fill, *rowptr, *bsum, *boff, *srcs;
    float2* eas;
    cudaGetSymbolAddress((void**)&P1,     g_P);
    cudaGetSymbolAddress((void**)&P2,     g_h);
    cudaGetSymbolAddress((void**)&cnt,    g_cnt);
    cudaGetSymbolAddress((void**)&fill,   g_fill);
    cudaGetSymbolAddress((void**)&rowptr, g_rowptr);
    cudaGetSymbolAddress((void**)&bsum,   g_bsum);
    cudaGetSymbolAddress((void**)&boff,   g_boff);
    cudaGetSymbolAddress((void**)&srcs,   g_src);
    cudaGetSymbolAddress((void**)&eas,    g_eas);

    const int blocks = (N + 127) / 128;
    const int nb = (N + 1023) / 1024;
    const int fused_smem = (128 * AG_LD + 2 * 32 * 128) * sizeof(float);  // 100352 B

    static int smem_set = 0;
    if (!smem_set) {
        cudaFuncSetAttribute(fused_kernel,
                             cudaFuncAttributeMaxDynamicSharedMemorySize, fused_smem);
        smem_set = 1;
    }

    // ---- CSR build (by dst), shared by both layers ----
    zero_cnt_kernel<<<(N + 255) / 256, 256>>>(cnt, fill, N);
    count_kernel<<<(E + 255) / 256, 256>>>(ei, cnt, E);
    scan_reduce_kernel<<<nb, 256>>>(cnt, bsum, N);
    scan_bsums_kernel<<<1, 32>>>(bsum, boff, nb, rowptr, N, E);
    scan_block_kernel<<<nb, 1024>>>(cnt, boff, rowptr, N);
    fill_kernel<<<(E + 255) / 256, 256>>>(ei, ea, rowptr, fill, srcs, eas, E);

    // ---- P1 = x @ W11x ----
    gemm_kernel<<<blocks, 256>>>(x, W11, P1, N, 64);

    // ---- L1 fused: gather(P1) -> h (smem) -> P2 = h @ W21x ----
    fused_kernel<<<blocks, 256, fused_smem>>>(
        rowptr, srcs, eas, P1,
        W11 + 64 * 128, W11 + 65 * 128, b11,
        W12, b12, 1,
        W21, P2, N);

    // ---- L2 fused: gather(P2) -> out = agg @ W22 + (deg+1) b22 ----
    fused_kernel<<<blocks, 256, fused_smem>>>(
        rowptr, srcs, eas, P2,
        W21 + 128 * 128, W21 + 129 * 128, b21,
        W22, b22, 0,
        nullptr, out, N);
}

// round 7
// speedup vs baseline: 1.1714x; 1.1714x over previous
#include <cuda_runtime.h>
#include <cuda_fp16.h>

// GIN model, algebraically restructured (R5 structure + fp16 P tables):
//   P = x@W1x stored fp16 (halves gather traffic); agg/h/out fp32.
//   conv(x) = segment_sum(relu(x[src]@W1x + ea@W1e + b1), dst) @ W2 + (deg+1)*b2
// CSR (by dst) built once; gather is atomic-free, one warp per node.

#define HD 128
#define MAX_N 100000
#define MAX_E 1600000
#define AS_LD 36

__device__ __half g_P[(long long)MAX_N * HD];   // fp16 pre-MLP table (both layers)
__device__ float  g_agg[(long long)MAX_N * HD]; // fp32 aggregation buffer
__device__ float  g_h[(long long)MAX_N * HD];   // fp32 layer-1 output
__device__ int    g_cnt[MAX_N];
__device__ int    g_fill[MAX_N];
__device__ int    g_rowptr[MAX_N + 1];
__device__ int    g_bsum[128];
__device__ int    g_boff[128];
__device__ int    g_src[MAX_E];
__device__ float2 g_eas[MAX_E];

typedef unsigned long long ull;

__device__ __forceinline__ ull pk2(float x, float y) {
    ull r; asm("mov.b64 %0, {%1, %2};" : "=l"(r) : "f"(x), "f"(y)); return r;
}
__device__ __forceinline__ void upk2(ull v, float& x, float& y) {
    asm("mov.b64 {%0, %1}, %2;" : "=f"(x), "=f"(y) : "l"(v));
}
__device__ __forceinline__ ull fma2(ull a, ull b, ull c) {
    ull d; asm("fma.rn.f32x2 %0, %1, %2, %3;" : "=l"(d) : "l"(a), "l"(b), "l"(c));
    return d;
}
__device__ __forceinline__ void cp16(void* smem_dst, const void* gsrc, int src_bytes) {
    unsigned s = (unsigned)__cvta_generic_to_shared(smem_dst);
    asm volatile("cp.async.ca.shared.global [%0], [%1], 16, %2;"
                 :: "r"(s), "l"(gsrc), "r"(src_bytes));
}
__device__ __forceinline__ void cp_commit() { asm volatile("cp.async.commit_group;"); }
template <int NN>
__device__ __forceinline__ void cp_wait() {
    asm volatile("cp.async.wait_group %0;" :: "n"(NN));
}

// ============================== CSR build ==================================
__global__ void zero_cnt_kernel(int* __restrict__ cnt, int* __restrict__ fill, int N) {
    int i = blockIdx.x * blockDim.x + threadIdx.x;
    if (i < N) { cnt[i] = 0; fill[i] = 0; }
}

__global__ void count_kernel(const int* __restrict__ ei, int* __restrict__ cnt, int E) {
    int e = blockIdx.x * blockDim.x + threadIdx.x;
    if (e < E) atomicAdd(&cnt[ei[E + e]], 1);
}

__global__ void scan_reduce_kernel(const int* __restrict__ cnt, int* __restrict__ bsum, int N) {
    __shared__ int sh[256];
    int base = blockIdx.x * 1024;
    int s = 0;
    for (int i = threadIdx.x; i < 1024; i += 256) {
        int idx = base + i;
        if (idx < N) s += cnt[idx];
    }
    sh[threadIdx.x] = s; __syncthreads();
    for (int off = 128; off > 0; off >>= 1) {
        if (threadIdx.x < off) sh[threadIdx.x] += sh[threadIdx.x + off];
        __syncthreads();
    }
    if (threadIdx.x == 0) bsum[blockIdx.x] = sh[0];
}

__global__ void scan_bsums_kernel(const int* __restrict__ bsum, int* __restrict__ boff,
                                  int nb, int* __restrict__ rowptr, int N, int E) {
    if (threadIdx.x == 0) {
        int run = 0;
        for (int i = 0; i < nb; ++i) { boff[i] = run; run += bsum[i]; }
        rowptr[N] = E;
    }
}

__global__ void scan_block_kernel(const int* __restrict__ cnt, const int* __restrict__ boff,
                                  int* __restrict__ rowptr, int N) {
    __shared__ int sh[1024];
    const int tid = threadIdx.x;
    const int idx = blockIdx.x * 1024 + tid;
    int v = (idx < N) ? cnt[idx] : 0;
    sh[tid] = v; __syncthreads();
#pragma unroll
    for (int off = 1; off < 1024; off <<= 1) {
        int t = (tid >= off) ? sh[tid - off] : 0;
        __syncthreads();
        sh[tid] += t;
        __syncthreads();
    }
    if (idx < N) rowptr[idx] = boff[blockIdx.x] + sh[tid] - v;
}

__global__ void fill_kernel(const int* __restrict__ ei, const float* __restrict__ ea,
                            const int* __restrict__ rowptr, int* __restrict__ fill,
                            int* __restrict__ srcs, float2* __restrict__ eas, int E) {
    int e = blockIdx.x * blockDim.x + threadIdx.x;
    if (e >= E) return;
    int dst = ei[E + e];
    int slot = rowptr[dst] + atomicAdd(&fill[dst], 1);
    srcs[slot] = ei[e];
    eas[slot] = make_float2(ea[2 * e], ea[2 * e + 1]);
}

// ================================ GEMM =====================================
// C[N,128] = A[N,K] @ W[K,128]; OutT = float (optionally (deg+1)*bias, relu)
// or __half (raw, for P tables). 256 thr, 128x128 tile, 8x8/thread, FFMA2.
struct alignas(16) H8 { __half2 a, b, c, d; };

template <typename OutT>
__global__ __launch_bounds__(256, 2)
void gemm_kernel(const float* __restrict__ A, const float* __restrict__ W,
                 OutT* __restrict__ C, int N, int K,
                 const float* __restrict__ bias, const int* __restrict__ rowptr,
                 int relu_flag)
{
    __shared__ float Ws[2][32][128];
    __shared__ float As[2][128][AS_LD];

    const int tid = threadIdx.x;
    const int tx = tid & 15;
    const int ty = tid >> 4;
    const int row0 = blockIdx.x * 128;

    const int wk = tid >> 5;
    const int wc = (tid & 31) * 4;
    const int ar = tid >> 1;
    const int ak = (tid & 1) * 16;

    ull acc[8][4];
#pragma unroll
    for (int r = 0; r < 8; ++r)
#pragma unroll
        for (int p = 0; p < 4; ++p) acc[r][p] = 0ULL;

    const int nt = K >> 5;

    auto load_tile = [&](int buf, int k0) {
#pragma unroll
        for (int j = 0; j < 4; ++j) {
            int kk = wk + j * 8;
            cp16(&Ws[buf][kk][wc], &W[(k0 + kk) * 128 + wc], 16);
        }
        int row = row0 + ar;
        int ok = (row < N) ? 16 : 0;
        const float* ap = &A[(long long)row * K + k0 + ak];
        cp16(&As[buf][ar][ak + 0],  ap + 0,  ok);
        cp16(&As[buf][ar][ak + 4],  ap + 4,  ok);
        cp16(&As[buf][ar][ak + 8],  ap + 8,  ok);
        cp16(&As[buf][ar][ak + 12], ap + 12, ok);
    };

    load_tile(0, 0);
    cp_commit();

    for (int t = 0; t < nt; ++t) {
        const int buf = t & 1;
        if (t + 1 < nt) {
            load_tile(buf ^ 1, (t + 1) * 32);
            cp_commit();
            cp_wait<1>();
        } else {
            cp_wait<0>();
        }
        __syncthreads();
#pragma unroll
        for (int k = 0; k < 32; ++k) {
            ulonglong2 wA = *(const ulonglong2*)&Ws[buf][k][tx * 8];
            ulonglong2 wB = *(const ulonglong2*)&Ws[buf][k][tx * 8 + 4];
#pragma unroll
            for (int r = 0; r < 8; ++r) {
                float a = As[buf][ty + 16 * r][k];   // drow=1 in warp: bank-safe
                ull aa = pk2(a, a);
                acc[r][0] = fma2(aa, wA.x, acc[r][0]);
                acc[r][1] = fma2(aa, wA.y, acc[r][1]);
                acc[r][2] = fma2(aa, wB.x, acc[r][2]);
                acc[r][3] = fma2(aa, wB.y, acc[r][3]);
            }
        }
        __syncthreads();
    }

    const int c0 = tx * 8;
#pragma unroll
    for (int r = 0; r < 8; ++r) {
        int row = row0 + ty + 16 * r;
        if (row >= N) continue;
        float v[8];
#pragma unroll
        for (int p = 0; p < 4; ++p) upk2(acc[r][p], v[2 * p], v[2 * p + 1]);
        if (bias) {
            float mult = 1.0f;
            if (rowptr) mult = (float)(rowptr[row + 1] - rowptr[row]) + 1.0f;
#pragma unroll
            for (int j = 0; j < 8; ++j) v[j] += mult * bias[c0 + j];
        }
        if (relu_flag) {
#pragma unroll
            for (int j = 0; j < 8; ++j) v[j] = fmaxf(v[j], 0.f);
        }
        if constexpr (sizeof(OutT) == 4) {
            float4* dst = (float4*)&C[(long long)row * 128 + c0];
            dst[0] = make_float4(v[0], v[1], v[2], v[3]);
            dst[1] = make_float4(v[4], v[5], v[6], v[7]);
        } else {
            H8 o;
            o.a = __floats2half2_rn(v[0], v[1]);
            o.b = __floats2half2_rn(v[2], v[3]);
            o.c = __floats2half2_rn(v[4], v[5]);
            o.d = __floats2half2_rn(v[6], v[7]);
            *(H8*)&C[(long long)row * 128 + c0] = o;
        }
    }
}

// ========================= CSR gather-aggregate ============================
// One warp per dst node; P is fp16 (256B/row gathered). Atomic-free.
__device__ __forceinline__ float4 ldP4(const __half* p) {
    uint2 raw = *(const uint2*)p;
    __half2 h0 = *(__half2*)&raw.x;
    __half2 h1 = *(__half2*)&raw.y;
    float2 f0 = __half22float2(h0);
    float2 f1 = __half22float2(h1);
    return make_float4(f0.x, f0.y, f1.x, f1.y);
}

__global__ __launch_bounds__(256)
void gather_kernel(const int* __restrict__ rowptr, const int* __restrict__ srcs,
                   const float2* __restrict__ eas,
                   const __half* __restrict__ P, float* __restrict__ agg,
                   const float* __restrict__ w0, const float* __restrict__ w1,
                   const float* __restrict__ b, int N)
{
    const int lane = threadIdx.x & 31;
    const int c = lane * 4;
    const int warp = blockIdx.x * (blockDim.x >> 5) + (threadIdx.x >> 5);
    const int nwarps = gridDim.x * (blockDim.x >> 5);

    const float4 wa = *(const float4*)(w0 + c);
    const float4 wb = *(const float4*)(w1 + c);
    const float4 bb = *(const float4*)(b + c);

    for (int n = warp; n < N; n += nwarps) {
        const int s = rowptr[n];
        const int e = rowptr[n + 1];

        // self loop (ea = 1,1)
        float4 ps = ldP4(P + (long long)n * HD + c);
        float4 acc;
        acc.x = fmaxf(ps.x + wa.x + wb.x + bb.x, 0.f);
        acc.y = fmaxf(ps.y + wa.y + wb.y + bb.y, 0.f);
        acc.z = fmaxf(ps.z + wa.z + wb.z + bb.z, 0.f);
        acc.w = fmaxf(ps.w + wa.w + wb.w + bb.w, 0.f);

        int j = s;
        for (; j + 4 <= e; j += 4) {
            int s0 = srcs[j], s1 = srcs[j + 1], s2 = srcs[j + 2], s3 = srcs[j + 3];
            float2 e0 = eas[j], e1 = eas[j + 1], e2 = eas[j + 2], e3 = eas[j + 3];
            float4 p0 = ldP4(P + (long long)s0 * HD + c);
            float4 p1 = ldP4(P + (long long)s1 * HD + c);
            float4 p2 = ldP4(P + (long long)s2 * HD + c);
            float4 p3 = ldP4(P + (long long)s3 * HD + c);
            acc.x += fmaxf(fmaf(e0.x, wa.x, fmaf(e0.y, wb.x, p0.x + bb.x)), 0.f);
            acc.y += fmaxf(fmaf(e0.x, wa.y, fmaf(e0.y, wb.y, p0.y + bb.y)), 0.f);
            acc.z += fmaxf(fmaf(e0.x, wa.z, fmaf(e0.y, wb.z, p0.z + bb.z)), 0.f);
            acc.w += fmaxf(fmaf(e0.x, wa.w, fmaf(e0.y, wb.w, p0.w + bb.w)), 0.f);
            acc.x += fmaxf(fmaf(e1.x, wa.x, fmaf(e1.y, wb.x, p1.x + bb.x)), 0.f);
            acc.y += fmaxf(fmaf(e1.x, wa.y, fmaf(e1.y, wb.y, p1.y + bb.y)), 0.f);
            acc.z += fmaxf(fmaf(e1.x, wa.z, fmaf(e1.y, wb.z, p1.z + bb.z)), 0.f);
            acc.w += fmaxf(fmaf(e1.x, wa.w, fmaf(e1.y, wb.w, p1.w + bb.w)), 0.f);
            acc.x += fmaxf(fmaf(e2.x, wa.x, fmaf(e2.y, wb.x, p2.x + bb.x)), 0.f);
            acc.y += fmaxf(fmaf(e2.x, wa.y, fmaf(e2.y, wb.y, p2.y + bb.y)), 0.f);
            acc.z += fmaxf(fmaf(e2.x, wa.z, fmaf(e2.y, wb.z, p2.z + bb.z)), 0.f);
            acc.w += fmaxf(fmaf(e2.x, wa.w, fmaf(e2.y, wb.w, p2.w + bb.w)), 0.f);
            acc.x += fmaxf(fmaf(e3.x, wa.x, fmaf(e3.y, wb.x, p3.x + bb.x)), 0.f);
            acc.y += fmaxf(fmaf(e3.x, wa.y, fmaf(e3.y, wb.y, p3.y + bb.y)), 0.f);
            acc.z += fmaxf(fmaf(e3.x, wa.z, fmaf(e3.y, wb.z, p3.z + bb.z)), 0.f);
            acc.w += fmaxf(fmaf(e3.x, wa.w, fmaf(e3.y, wb.w, p3.w + bb.w)), 0.f);
        }
        for (; j < e; ++j) {
            int sj = srcs[j];
            float2 ej = eas[j];
            float4 p = ldP4(P + (long long)sj * HD + c);
            acc.x += fmaxf(fmaf(ej.x, wa.x, fmaf(ej.y, wb.x, p.x + bb.x)), 0.f);
            acc.y += fmaxf(fmaf(ej.x, wa.y, fmaf(ej.y, wb.y, p.y + bb.y)), 0.f);
            acc.z += fmaxf(fmaf(ej.x, wa.z, fmaf(ej.y, wb.z, p.z + bb.z)), 0.f);
            acc.w += fmaxf(fmaf(ej.x, wa.w, fmaf(ej.y, wb.w, p.w + bb.w)), 0.f);
        }
        *(float4*)(agg + (long long)n * HD + c) = acc;
    }
}

// ---------------------------------------------------------------------------
extern "C" void kernel_launch(void* const* d_in, const int* in_sizes, int n_in,
                              void* d_out, int out_size)
{
    const float* x   = (const float*)d_in[0];
    const int*   ei  = (const int*)d_in[1];
    const float* ea  = (const float*)d_in[2];
    const float* W11 = (const float*)d_in[3];
    const float* b11 = (const float*)d_in[4];
    const float* W12 = (const float*)d_in[5];
    const float* b12 = (const float*)d_in[6];
    const float* W21 = (const float*)d_in[7];
    const float* b21 = (const float*)d_in[8];
    const float* W22 = (const float*)d_in[9];
    const float* b22 = (const float*)d_in[10];
    float* out = (float*)d_out;

    const int IN_DIM = 64;
    const int N = in_sizes[0] / IN_DIM;
    const int E = in_sizes[1] / 2;

    __half* P;
    float *agg, *h;
    int *cnt, *fill, *rowptr, *bsum, *boff, *srcs;
    float2* eas;
    cudaGetSymbolAddress((void**)&P,      g_P);
    cudaGetSymbolAddress((void**)&agg,    g_agg);
    cudaGetSymbolAddress((void**)&h,      g_h);
    cudaGetSymbolAddress((void**)&cnt,    g_cnt);
    cudaGetSymbolAddress((void**)&fill,   g_fill);
    cudaGetSymbolAddress((void**)&rowptr, g_rowptr);
    cudaGetSymbolAddress((void**)&bsum,   g_bsum);
    cudaGetSymbolAddress((void**)&boff,   g_boff);
    cudaGetSymbolAddress((void**)&srcs,   g_src);
    cudaGetSymbolAddress((void**)&eas,    g_eas);

    const int gemm_blocks = (N + 127) / 128;
    const int gath_blocks = 148 * 16;
    const int nb = (N + 1023) / 1024;

    // ---- CSR build (by dst), shared by both layers ----
    zero_cnt_kernel<<<(N + 255) / 256, 256>>>(cnt, fill, N);
    count_kernel<<<(E + 255) / 256, 256>>>(ei, cnt, E);
    scan_reduce_kernel<<<nb, 256>>>(cnt, bsum, N);
    scan_bsums_kernel<<<1, 32>>>(bsum, boff, nb, rowptr, N, E);
    scan_block_kernel<<<nb, 1024>>>(cnt, boff, rowptr, N);
    fill_kernel<<<(E + 255) / 256, 256>>>(ei, ea, rowptr, fill, srcs, eas, E);

    // ---- layer 1 ----
    gemm_kernel<__half><<<gemm_blocks, 256>>>(x, W11, P, N, 64,
                                              nullptr, nullptr, 0);
    gather_kernel<<<gath_blocks, 256>>>(rowptr, srcs, eas, P, agg,
                                        W11 + 64 * 128, W11 + 65 * 128, b11, N);
    gemm_kernel<float><<<gemm_blocks, 256>>>(agg, W12, h, N, 128,
                                             b12, rowptr, 1);

    // ---- layer 2 ----
    gemm_kernel<__half><<<gemm_blocks, 256>>>(h, W21, P, N, 128,
                                              nullptr, nullptr, 0);
    gather_kernel<<<gath_blocks, 256>>>(rowptr, srcs, eas, P, agg,
                                        W21 + 128 * 128, W21 + 129 * 128, b21, N);
    gemm_kernel<float><<<gemm_blocks, 256>>>(agg, W22, out, N, 128,
                                             b22, rowptr, 0);
}

// round 8
// speedup vs baseline: 1.8073x; 1.5429x over previous
#include <cuda_runtime.h>
#include <cuda_fp16.h>

// GIN model, restructured:
//   conv(x) = segment_sum(relu(x[src]@W1x + ea@W1e + b1), dst) @ W2 + (deg+1)*b2
// Node tables (P/agg/h/x) stored fp16; GEMMs on tensor cores
// (mma.m16n8k16 fp16->fp32); CSR-bucketed atomic-free gather.

#define HD 128
#define MAX_N 100000
#define MAX_E 1600000

__device__ __half g_P[(long long)MAX_N * HD];     // pre-MLP table
__device__ __half g_agg16[(long long)MAX_N * HD]; // aggregation (fp16)
__device__ __half g_h16[(long long)MAX_N * HD];   // layer-1 output (fp16)
__device__ __half g_x16[(long long)MAX_N * 64];   // x converted to fp16
__device__ __half g_wt11[128 * 64];               // W11x^T fp16 [n][k]
__device__ __half g_wt12[128 * 128];              // W12^T
__device__ __half g_wt21[128 * 128];              // W21x^T
__device__ __half g_wt22[128 * 128];              // W22^T
__device__ int    g_cnt[MAX_N];
__device__ int    g_fill[MAX_N];
__device__ int    g_rowptr[MAX_N + 1];
__device__ int    g_bsum[128];
__device__ int    g_boff[128];
__device__ int    g_src[MAX_E];
__device__ float2 g_eas[MAX_E];

__device__ __forceinline__ void cp16(void* smem_dst, const void* gsrc, int src_bytes) {
    unsigned s = (unsigned)__cvta_generic_to_shared(smem_dst);
    asm volatile("cp.async.ca.shared.global [%0], [%1], 16, %2;"
                 :: "r"(s), "l"(gsrc), "r"(src_bytes));
}
__device__ __forceinline__ void cp_commit() { asm volatile("cp.async.commit_group;"); }
template <int NN>
__device__ __forceinline__ void cp_wait() {
    asm volatile("cp.async.wait_group %0;" :: "n"(NN));
}
__device__ __forceinline__ void mma16816(float* d, const unsigned* a, const unsigned* b) {
    asm volatile("mma.sync.aligned.m16n8k16.row.col.f32.f16.f16.f32 "
                 "{%0,%1,%2,%3}, {%4,%5,%6,%7}, {%8,%9}, {%0,%1,%2,%3};"
                 : "+f"(d[0]), "+f"(d[1]), "+f"(d[2]), "+f"(d[3])
                 : "r"(a[0]), "r"(a[1]), "r"(a[2]), "r"(a[3]),
                   "r"(b[0]), "r"(b[1]));
}

// ============================== CSR build ==================================
__global__ void zero_cnt_kernel(int* __restrict__ cnt, int* __restrict__ fill, int N) {
    int i = blockIdx.x * blockDim.x + threadIdx.x;
    if (i < N) { cnt[i] = 0; fill[i] = 0; }
}
__global__ void count_kernel(const int* __restrict__ ei, int* __restrict__ cnt, int E) {
    int e = blockIdx.x * blockDim.x + threadIdx.x;
    if (e < E) atomicAdd(&cnt[ei[E + e]], 1);
}
__global__ void scan_reduce_kernel(const int* __restrict__ cnt, int* __restrict__ bsum, int N) {
    __shared__ int sh[256];
    int base = blockIdx.x * 1024;
    int s = 0;
    for (int i = threadIdx.x; i < 1024; i += 256) {
        int idx = base + i;
        if (idx < N) s += cnt[idx];
    }
    sh[threadIdx.x] = s; __syncthreads();
    for (int off = 128; off > 0; off >>= 1) {
        if (threadIdx.x < off) sh[threadIdx.x] += sh[threadIdx.x + off];
        __syncthreads();
    }
    if (threadIdx.x == 0) bsum[blockIdx.x] = sh[0];
}
__global__ void scan_bsums_kernel(const int* __restrict__ bsum, int* __restrict__ boff,
                                  int nb, int* __restrict__ rowptr, int N, int E) {
    if (threadIdx.x == 0) {
        int run = 0;
        for (int i = 0; i < nb; ++i) { boff[i] = run; run += bsum[i]; }
        rowptr[N] = E;
    }
}
__global__ void scan_block_kernel(const int* __restrict__ cnt, const int* __restrict__ boff,
                                  int* __restrict__ rowptr, int N) {
    __shared__ int sh[1024];
    const int tid = threadIdx.x;
    const int idx = blockIdx.x * 1024 + tid;
    int v = (idx < N) ? cnt[idx] : 0;
    sh[tid] = v; __syncthreads();
#pragma unroll
    for (int off = 1; off < 1024; off <<= 1) {
        int t = (tid >= off) ? sh[tid - off] : 0;
        __syncthreads();
        sh[tid] += t;
        __syncthreads();
    }
    if (idx < N) rowptr[idx] = boff[blockIdx.x] + sh[tid] - v;
}
__global__ void fill_kernel(const int* __restrict__ ei, const float* __restrict__ ea,
                            const int* __restrict__ rowptr, int* __restrict__ fill,
                            int* __restrict__ srcs, float2* __restrict__ eas, int E) {
    int e = blockIdx.x * blockDim.x + threadIdx.x;
    if (e >= E) return;
    int dst = ei[E + e];
    int slot = rowptr[dst] + atomicAdd(&fill[dst], 1);
    srcs[slot] = ei[e];
    eas[slot] = make_float2(ea[2 * e], ea[2 * e + 1]);
}

// ========================= conversion prepasses ============================
__global__ void cvt_x_kernel(const float* __restrict__ x, __half* __restrict__ xh, int n4) {
    int i = blockIdx.x * blockDim.x + threadIdx.x;
    if (i < n4) {
        float4 v = ((const float4*)x)[i];
        __half2 a = __floats2half2_rn(v.x, v.y);
        __half2 b = __floats2half2_rn(v.z, v.w);
        uint2 o;
        o.x = *(unsigned*)&a;
        o.y = *(unsigned*)&b;
        ((uint2*)xh)[i] = o;
    }
}
// Wt[n][k] = W[k][n] (fp32 row-major [K][128] -> fp16 [128][K])
__global__ void cvt_wt_kernel(const float* __restrict__ W, __half* __restrict__ Wt, int K) {
    int idx = blockIdx.x * blockDim.x + threadIdx.x;
    if (idx < 128 * K) {
        int n = idx / K, k = idx - n * K;
        Wt[idx] = __float2half(W[k * 128 + n]);
    }
}

// ======================= tensor-core GEMM ==================================
// C[N,128] = A[N,K](fp16) @ Wt^T (Wt fp16 [128][K]); fp32 accum.
// 256 thr = 8 warps (4 row x 2 col), block tile 128x128, warp tile 32x64.
template <int K, typename OutT, bool BIAS, bool RELU>
__global__ __launch_bounds__(256, 2)
void hgemm_kernel(const __half* __restrict__ A, const __half* __restrict__ Wt,
                  OutT* __restrict__ C, const float* __restrict__ bias,
                  const int* __restrict__ rowptr, int N)
{
    constexpr int BS_LD = K + 8;   // halves; banks for frag reads: 4n + k/2
    constexpr int AS_LD = 40;      // halves; banks: 20r + k/2 (conflict-free)
    extern __shared__ __half sh[];
    __half* Bs = sh;                       // [128][BS_LD]
    __half* As = sh + 128 * BS_LD;         // [2][128][AS_LD]

    const int tid  = threadIdx.x;
    const int lane = tid & 31;
    const int wid  = tid >> 5;
    const int wm   = (wid & 3) * 32;
    const int wn   = (wid >> 2) * 64;
    const int row0 = blockIdx.x * 128;

    // load whole Wt (128 x K halves)
    {
        int r = tid >> 1;
        int cb = (tid & 1) * (K / 2);
#pragma unroll
        for (int j = 0; j < K / 16; ++j)
            cp16(&Bs[r * BS_LD + cb + j * 8], &Wt[r * K + cb + j * 8], 16);
    }
    auto loadA = [&](int buf, int k0) {
        int r = tid >> 1;
        int h0 = (tid & 1) * 16;
        int row = row0 + r;
        int ok = (row < N) ? 16 : 0;
        const __half* ap = &A[(long long)row * K + k0 + h0];
        __half* dp = &As[(buf * 128 + r) * AS_LD + h0];
        cp16(dp,     ap,     ok);
        cp16(dp + 8, ap + 8, ok);
    };
    loadA(0, 0);
    cp_commit();

    float d[2][8][4];
#pragma unroll
    for (int i = 0; i < 2; ++i)
#pragma unroll
        for (int j = 0; j < 8; ++j)
#pragma unroll
            for (int p = 0; p < 4; ++p) d[i][j][p] = 0.f;

    const int r_ = lane >> 2;
    const int c_ = (lane & 3) * 2;
    constexpr int nt = K / 32;

#pragma unroll 1
    for (int t = 0; t < nt; ++t) {
        const int buf = t & 1;
        if (t + 1 < nt) { loadA(buf ^ 1, (t + 1) * 32); cp_commit(); cp_wait<1>(); }
        else            { cp_wait<0>(); }
        __syncthreads();
#pragma unroll
        for (int ks = 0; ks < 2; ++ks) {
            const int kk = ks * 16;
            unsigned a[2][4], b[8][2];
#pragma unroll
            for (int i = 0; i < 2; ++i) {
                const __half* base = &As[(buf * 128 + wm + i * 16 + r_) * AS_LD + kk + c_];
                a[i][0] = *(const unsigned*)base;
                a[i][1] = *(const unsigned*)(base + 8 * AS_LD);
                a[i][2] = *(const unsigned*)(base + 8);
                a[i][3] = *(const unsigned*)(base + 8 * AS_LD + 8);
            }
#pragma unroll
            for (int j = 0; j < 8; ++j) {
                const __half* bb = &Bs[(wn + j * 8 + r_) * BS_LD + t * 32 + kk + c_];
                b[j][0] = *(const unsigned*)bb;
                b[j][1] = *(const unsigned*)(bb + 8);
            }
#pragma unroll
            for (int i = 0; i < 2; ++i)
#pragma unroll
                for (int j = 0; j < 8; ++j)
                    mma16816(d[i][j], a[i], b[j]);
        }
        __syncthreads();
    }

    // epilogue: c0,c1 -> (row, col..col+1); c2,c3 -> (row+8, ...)
#pragma unroll
    for (int i = 0; i < 2; ++i) {
#pragma unroll
        for (int hf = 0; hf < 2; ++hf) {
            int row = row0 + wm + i * 16 + hf * 8 + r_;
            if (row >= N) continue;
            float mult = 0.f;
            if (BIAS) mult = (float)(rowptr[row + 1] - rowptr[row]) + 1.0f;
#pragma unroll
            for (int j = 0; j < 8; ++j) {
                float v0 = d[i][j][hf * 2 + 0];
                float v1 = d[i][j][hf * 2 + 1];
                int col = wn + j * 8 + c_;
                if (BIAS) { v0 += mult * bias[col]; v1 += mult * bias[col + 1]; }
                if (RELU) { v0 = fmaxf(v0, 0.f); v1 = fmaxf(v1, 0.f); }
                if constexpr (sizeof(OutT) == 2) {
                    __half2 hv = __floats2half2_rn(v0, v1);
                    *(__half2*)((__half*)C + (long long)row * 128 + col) = hv;
                } else {
                    *(float2*)((float*)C + (long long)row * 128 + col) = make_float2(v0, v1);
                }
            }
        }
    }
}

// ========================= CSR gather-aggregate ============================
__device__ __forceinline__ float4 ldP4(const __half* p) {
    uint2 raw = *(const uint2*)p;
    __half2 h0 = *(__half2*)&raw.x;
    __half2 h1 = *(__half2*)&raw.y;
    float2 f0 = __half22float2(h0);
    float2 f1 = __half22float2(h1);
    return make_float4(f0.x, f0.y, f1.x, f1.y);
}

__global__ __launch_bounds__(256)
void gather_kernel(const int* __restrict__ rowptr, const int* __restrict__ srcs,
                   const float2* __restrict__ eas,
                   const __half* __restrict__ P, __half* __restrict__ agg,
                   const float* __restrict__ w0, const float* __restrict__ w1,
                   const float* __restrict__ b, int N)
{
    const int lane = threadIdx.x & 31;
    const int c = lane * 4;
    const int warp = blockIdx.x * (blockDim.x >> 5) + (threadIdx.x >> 5);
    const int nwarps = gridDim.x * (blockDim.x >> 5);

    const float4 wa = *(const float4*)(w0 + c);
    const float4 wb = *(const float4*)(w1 + c);
    const float4 bb = *(const float4*)(b + c);

    for (int n = warp; n < N; n += nwarps) {
        const int s = rowptr[n];
        const int e = rowptr[n + 1];

        float4 ps = ldP4(P + (long long)n * HD + c);
        float4 acc;
        acc.x = fmaxf(ps.x + wa.x + wb.x + bb.x, 0.f);
        acc.y = fmaxf(ps.y + wa.y + wb.y + bb.y, 0.f);
        acc.z = fmaxf(ps.z + wa.z + wb.z + bb.z, 0.f);
        acc.w = fmaxf(ps.w + wa.w + wb.w + bb.w, 0.f);

        int j = s;
        for (; j + 4 <= e; j += 4) {
            int s0 = srcs[j], s1 = srcs[j + 1], s2 = srcs[j + 2], s3 = srcs[j + 3];
            float2 e0 = eas[j], e1 = eas[j + 1], e2 = eas[j + 2], e3 = eas[j + 3];
            float4 p0 = ldP4(P + (long long)s0 * HD + c);
            float4 p1 = ldP4(P + (long long)s1 * HD + c);
            float4 p2 = ldP4(P + (long long)s2 * HD + c);
            float4 p3 = ldP4(P + (long long)s3 * HD + c);
            acc.x += fmaxf(fmaf(e0.x, wa.x, fmaf(e0.y, wb.x, p0.x + bb.x)), 0.f);
            acc.y += fmaxf(fmaf(e0.x, wa.y, fmaf(e0.y, wb.y, p0.y + bb.y)), 0.f);
            acc.z += fmaxf(fmaf(e0.x, wa.z, fmaf(e0.y, wb.z, p0.z + bb.z)), 0.f);
            acc.w += fmaxf(fmaf(e0.x, wa.w, fmaf(e0.y, wb.w, p0.w + bb.w)), 0.f);
            acc.x += fmaxf(fmaf(e1.x, wa.x, fmaf(e1.y, wb.x, p1.x + bb.x)), 0.f);
            acc.y += fmaxf(fmaf(e1.x, wa.y, fmaf(e1.y, wb.y, p1.y + bb.y)), 0.f);
            acc.z += fmaxf(fmaf(e1.x, wa.z, fmaf(e1.y, wb.z, p1.z + bb.z)), 0.f);
            acc.w += fmaxf(fmaf(e1.x, wa.w, fmaf(e1.y, wb.w, p1.w + bb.w)), 0.f);
            acc.x += fmaxf(fmaf(e2.x, wa.x, fmaf(e2.y, wb.x, p2.x + bb.x)), 0.f);
            acc.y += fmaxf(fmaf(e2.x, wa.y, fmaf(e2.y, wb.y, p2.y + bb.y)), 0.f);
            acc.z += fmaxf(fmaf(e2.x, wa.z, fmaf(e2.y, wb.z, p2.z + bb.z)), 0.f);
            acc.w += fmaxf(fmaf(e2.x, wa.w, fmaf(e2.y, wb.w, p2.w + bb.w)), 0.f);
            acc.x += fmaxf(fmaf(e3.x, wa.x, fmaf(e3.y, wb.x, p3.x + bb.x)), 0.f);
            acc.y += fmaxf(fmaf(e3.x, wa.y, fmaf(e3.y, wb.y, p3.y + bb.y)), 0.f);
            acc.z += fmaxf(fmaf(e3.x, wa.z, fmaf(e3.y, wb.z, p3.z + bb.z)), 0.f);
            acc.w += fmaxf(fmaf(e3.x, wa.w, fmaf(e3.y, wb.w, p3.w + bb.w)), 0.f);
        }
        for (; j < e; ++j) {
            int sj = srcs[j];
            float2 ej = eas[j];
            float4 p = ldP4(P + (long long)sj * HD + c);
            acc.x += fmaxf(fmaf(ej.x, wa.x, fmaf(ej.y, wb.x, p.x + bb.x)), 0.f);
            acc.y += fmaxf(fmaf(ej.x, wa.y, fmaf(ej.y, wb.y, p.y + bb.y)), 0.f);
            acc.z += fmaxf(fmaf(ej.x, wa.z, fmaf(ej.y, wb.z, p.z + bb.z)), 0.f);
            acc.w += fmaxf(fmaf(ej.x, wa.w, fmaf(ej.y, wb.w, p.w + bb.w)), 0.f);
        }
        __half2 o0 = __floats2half2_rn(acc.x, acc.y);
        __half2 o1 = __floats2half2_rn(acc.z, acc.w);
        uint2 st;
        st.x = *(unsigned*)&o0;
        st.y = *(unsigned*)&o1;
        *(uint2*)(agg + (long long)n * HD + c) = st;
    }
}

// ---------------------------------------------------------------------------
extern "C" void kernel_launch(void* const* d_in, const int* in_sizes, int n_in,
                              void* d_out, int out_size)
{
    const float* x   = (const float*)d_in[0];
    const int*   ei  = (const int*)d_in[1];
    const float* ea  = (const float*)d_in[2];
    const float* W11 = (const float*)d_in[3];
    const float* b11 = (const float*)d_in[4];
    const float* W12 = (const float*)d_in[5];
    const float* b12 = (const float*)d_in[6];
    const float* W21 = (const float*)d_in[7];
    const float* b21 = (const float*)d_in[8];
    const float* W22 = (const float*)d_in[9];
    const float* b22 = (const float*)d_in[10];
    float* out = (float*)d_out;

    const int IN_DIM = 64;
    const int N = in_sizes[0] / IN_DIM;
    const int E = in_sizes[1] / 2;

    __half *P, *agg16, *h16, *x16, *wt11, *wt12, *wt21, *wt22;
    int *cnt, *fill, *rowptr, *bsum, *boff, *srcs;
    float2* eas;
    cudaGetSymbolAddress((void**)&P,      g_P);
    cudaGetSymbolAddress((void**)&agg16,  g_agg16);
    cudaGetSymbolAddress((void**)&h16,    g_h16);
    cudaGetSymbolAddress((void**)&x16,    g_x16);
    cudaGetSymbolAddress((void**)&wt11,   g_wt11);
    cudaGetSymbolAddress((void**)&wt12,   g_wt12);
    cudaGetSymbolAddress((void**)&wt21,   g_wt21);
    cudaGetSymbolAddress((void**)&wt22,   g_wt22);
    cudaGetSymbolAddress((void**)&cnt,    g_cnt);
    cudaGetSymbolAddress((void**)&fill,   g_fill);
    cudaGetSymbolAddress((void**)&rowptr, g_rowptr);
    cudaGetSymbolAddress((void**)&bsum,   g_bsum);
    cudaGetSymbolAddress((void**)&boff,   g_boff);
    cudaGetSymbolAddress((void**)&srcs,   g_src);
    cudaGetSymbolAddress((void**)&eas,    g_eas);

    const int gemm_blocks = (N + 127) / 128;
    const int gath_blocks = 148 * 16;
    const int nb = (N + 1023) / 1024;
    const int smem128 = (128 * (128 + 8) + 2 * 128 * 40) * 2;  // 55296 B
    const int smem64  = (128 * (64 + 8)  + 2 * 128 * 40) * 2;  // 38912 B

    static int attr_set = 0;
    if (!attr_set) {
        cudaFuncSetAttribute(hgemm_kernel<64,  __half, false, false>,
                             cudaFuncAttributeMaxDynamicSharedMemorySize, smem64);
        cudaFuncSetAttribute(hgemm_kernel<128, __half, true,  true>,
                             cudaFuncAttributeMaxDynamicSharedMemorySize, smem128);
        cudaFuncSetAttribute(hgemm_kernel<128, __half, false, false>,
                             cudaFuncAttributeMaxDynamicSharedMemorySize, smem128);
        cudaFuncSetAttribute(hgemm_kernel<128, float,  true,  false>,
                             cudaFuncAttributeMaxDynamicSharedMemorySize, smem128);
        attr_set = 1;
    }

    // ---- CSR build ----
    zero_cnt_kernel<<<(N + 255) / 256, 256>>>(cnt, fill, N);
    count_kernel<<<(E + 255) / 256, 256>>>(ei, cnt, E);
    scan_reduce_kernel<<<nb, 256>>>(cnt, bsum, N);
    scan_bsums_kernel<<<1, 32>>>(bsum, boff, nb, rowptr, N, E);
    scan_block_kernel<<<nb, 1024>>>(cnt, boff, rowptr, N);
    fill_kernel<<<(E + 255) / 256, 256>>>(ei, ea, rowptr, fill, srcs, eas, E);

    // ---- conversions ----
    cvt_x_kernel<<<(N * 16 + 255) / 256, 256>>>(x, x16, N * 16);
    cvt_wt_kernel<<<(128 * 64 + 255) / 256, 256>>>(W11, wt11, 64);
    cvt_wt_kernel<<<(128 * 128 + 255) / 256, 256>>>(W12, wt12, 128);
    cvt_wt_kernel<<<(128 * 128 + 255) / 256, 256>>>(W21, wt21, 128);
    cvt_wt_kernel<<<(128 * 128 + 255) / 256, 256>>>(W22, wt22, 128);

    // ---- layer 1 ----
    hgemm_kernel<64, __half, false, false><<<gemm_blocks, 256, smem64>>>(
        x16, wt11, P, nullptr, nullptr, N);
    gather_kernel<<<gath_blocks, 256>>>(rowptr, srcs, eas, P, agg16,
                                        W11 + 64 * 128, W11 + 65 * 128, b11, N);
    hgemm_kernel<128, __half, true, true><<<gemm_blocks, 256, smem128>>>(
        agg16, wt12, h16, b12, rowptr, N);

    // ---- layer 2 ----
    hgemm_kernel<128, __half, false, false><<<gemm_blocks, 256, smem128>>>(
        h16, wt21, P, nullptr, nullptr, N);
    gather_kernel<<<gath_blocks, 256>>>(rowptr, srcs, eas, P, agg16,
                                        W21 + 128 * 128, W21 + 129 * 128, b21, N);
    hgemm_kernel<128, float, true, false><<<gemm_blocks, 256, smem128>>>(
        agg16, wt22, out, b22, rowptr, N);
}

// round 9
// speedup vs baseline: 1.8638x; 1.0312x over previous
#include <cuda_runtime.h>
#include <cuda_fp16.h>

// GIN model, restructured:
//   conv(x) = segment_sum(relu(x[src]@W1x + ea@W1e + b1), dst) @ W2 + (deg+1)*b2
// Node tables fp16; GEMMs on tensor cores (mma.m16n8k16 f16->f32);
// CSR-bucketed atomic-free gather with 8-deep load pipelining.

#define HD 128
#define MAX_N 100000
#define MAX_E 1600000

__device__ __half g_P[(long long)MAX_N * HD];     // pre-MLP table
__device__ __half g_agg16[(long long)MAX_N * HD]; // aggregation (fp16)
__device__ __half g_h16[(long long)MAX_N * HD];   // layer-1 output (fp16)
__device__ __half g_x16[(long long)MAX_N * 64];   // x converted to fp16
__device__ __half g_wt11[128 * 64];               // W11x^T fp16 [n][k]
__device__ __half g_wt12[128 * 128];              // W12^T
__device__ __half g_wt21[128 * 128];              // W21x^T
__device__ __half g_wt22[128 * 128];              // W22^T
__device__ int    g_cnt[MAX_N];
__device__ int    g_fill[MAX_N];
__device__ int    g_rowptr[MAX_N + 1];
__device__ int    g_bsum[128];
__device__ int    g_boff[128];
__device__ int    g_src[MAX_E];
__device__ float2 g_eas[MAX_E];

__device__ __forceinline__ void cp16(void* smem_dst, const void* gsrc, int src_bytes) {
    unsigned s = (unsigned)__cvta_generic_to_shared(smem_dst);
    asm volatile("cp.async.ca.shared.global [%0], [%1], 16, %2;"
                 :: "r"(s), "l"(gsrc), "r"(src_bytes));
}
__device__ __forceinline__ void cp_commit() { asm volatile("cp.async.commit_group;"); }
template <int NN>
__device__ __forceinline__ void cp_wait() {
    asm volatile("cp.async.wait_group %0;" :: "n"(NN));
}
__device__ __forceinline__ void mma16816(float* d, const unsigned* a, const unsigned* b) {
    asm volatile("mma.sync.aligned.m16n8k16.row.col.f32.f16.f16.f32 "
                 "{%0,%1,%2,%3}, {%4,%5,%6,%7}, {%8,%9}, {%0,%1,%2,%3};"
                 : "+f"(d[0]), "+f"(d[1]), "+f"(d[2]), "+f"(d[3])
                 : "r"(a[0]), "r"(a[1]), "r"(a[2]), "r"(a[3]),
                   "r"(b[0]), "r"(b[1]));
}

// ============================== CSR build ==================================
__global__ void count_kernel(const int* __restrict__ ei, int* __restrict__ cnt, int E) {
    int e = blockIdx.x * blockDim.x + threadIdx.x;
    if (e < E) atomicAdd(&cnt[ei[E + e]], 1);
}
__global__ void scan_reduce_kernel(const int* __restrict__ cnt, int* __restrict__ bsum, int N) {
    __shared__ int sh[256];
    int base = blockIdx.x * 1024;
    int s = 0;
    for (int i = threadIdx.x; i < 1024; i += 256) {
        int idx = base + i;
        if (idx < N) s += cnt[idx];
    }
    sh[threadIdx.x] = s; __syncthreads();
    for (int off = 128; off > 0; off >>= 1) {
        if (threadIdx.x < off) sh[threadIdx.x] += sh[threadIdx.x + off];
        __syncthreads();
    }
    if (threadIdx.x == 0) bsum[blockIdx.x] = sh[0];
}
// parallel exclusive scan of block sums (nb <= 128)
__global__ void scan_bsums_kernel(const int* __restrict__ bsum, int* __restrict__ boff,
                                  int nb, int* __restrict__ rowptr, int N, int E) {
    __shared__ int sh[128];
    int t = threadIdx.x;
    int v = (t < nb) ? bsum[t] : 0;
    sh[t] = v; __syncthreads();
#pragma unroll
    for (int off = 1; off < 128; off <<= 1) {
        int u = (t >= off) ? sh[t - off] : 0;
        __syncthreads();
        sh[t] += u;
        __syncthreads();
    }
    if (t < nb) boff[t] = sh[t] - v;   // exclusive
    if (t == 0) rowptr[N] = E;
}
__global__ void scan_block_kernel(const int* __restrict__ cnt, const int* __restrict__ boff,
                                  int* __restrict__ rowptr, int N) {
    __shared__ int sh[1024];
    const int tid = threadIdx.x;
    const int idx = blockIdx.x * 1024 + tid;
    int v = (idx < N) ? cnt[idx] : 0;
    sh[tid] = v; __syncthreads();
#pragma unroll
    for (int off = 1; off < 1024; off <<= 1) {
        int t = (tid >= off) ? sh[tid - off] : 0;
        __syncthreads();
        sh[tid] += t;
        __syncthreads();
    }
    if (idx < N) rowptr[idx] = boff[blockIdx.x] + sh[tid] - v;
}
__global__ void fill_kernel(const int* __restrict__ ei, const float* __restrict__ ea,
                            const int* __restrict__ rowptr, int* __restrict__ fill,
                            int* __restrict__ srcs, float2* __restrict__ eas, int E) {
    int e = blockIdx.x * blockDim.x + threadIdx.x;
    if (e >= E) return;
    int dst = ei[E + e];
    int slot = rowptr[dst] + atomicAdd(&fill[dst], 1);
    srcs[slot] = ei[e];
    eas[slot] = make_float2(ea[2 * e], ea[2 * e + 1]);
}

// ========================= conversion prepasses ============================
__global__ void cvt_x_kernel(const float* __restrict__ x, __half* __restrict__ xh, int n4) {
    int i = blockIdx.x * blockDim.x + threadIdx.x;
    if (i < n4) {
        float4 v = ((const float4*)x)[i];
        __half2 a = __floats2half2_rn(v.x, v.y);
        __half2 b = __floats2half2_rn(v.z, v.w);
        uint2 o;
        o.x = *(unsigned*)&a;
        o.y = *(unsigned*)&b;
        ((uint2*)xh)[i] = o;
    }
}
// all four weight transposes in one launch
__global__ void cvt_weights_kernel(const float* __restrict__ W11, const float* __restrict__ W12,
                                   const float* __restrict__ W21, const float* __restrict__ W22,
                                   __half* __restrict__ wt11, __half* __restrict__ wt12,
                                   __half* __restrict__ wt21, __half* __restrict__ wt22) {
    int idx = blockIdx.x * blockDim.x + threadIdx.x;
    if (idx < 8192) {                                   // W11: 128 x 64
        int n = idx >> 6, k = idx & 63;
        wt11[idx] = __float2half(W11[k * 128 + n]);
    } else if (idx < 8192 + 16384) {
        int i = idx - 8192;
        int n = i >> 7, k = i & 127;
        wt12[i] = __float2half(W12[k * 128 + n]);
    } else if (idx < 8192 + 32768) {
        int i = idx - 8192 - 16384;
        int n = i >> 7, k = i & 127;
        wt21[i] = __float2half(W21[k * 128 + n]);
    } else if (idx < 8192 + 49152) {
        int i = idx - 8192 - 32768;
        int n = i >> 7, k = i & 127;
        wt22[i] = __float2half(W22[k * 128 + n]);
    }
}

// ======================= tensor-core GEMM ==================================
// C[N,128] = A[N,K](fp16) @ Wt^T (Wt fp16 [128][K]); fp32 accum.
template <int K, typename OutT, bool BIAS, bool RELU>
__global__ __launch_bounds__(256, 2)
void hgemm_kernel(const __half* __restrict__ A, const __half* __restrict__ Wt,
                  OutT* __restrict__ C, const float* __restrict__ bias,
                  const int* __restrict__ rowptr, int N)
{
    constexpr int BS_LD = K + 8;
    constexpr int AS_LD = 40;
    extern __shared__ __half sh[];
    __half* Bs = sh;                       // [128][BS_LD]
    __half* As = sh + 128 * BS_LD;         // [2][128][AS_LD]

    const int tid  = threadIdx.x;
    const int lane = tid & 31;
    const int wid  = tid >> 5;
    const int wm   = (wid & 3) * 32;
    const int wn   = (wid >> 2) * 64;
    const int row0 = blockIdx.x * 128;

    {
        int r = tid >> 1;
        int cb = (tid & 1) * (K / 2);
#pragma unroll
        for (int j = 0; j < K / 16; ++j)
            cp16(&Bs[r * BS_LD + cb + j * 8], &Wt[r * K + cb + j * 8], 16);
    }
    auto loadA = [&](int buf, int k0) {
        int r = tid >> 1;
        int h0 = (tid & 1) * 16;
        int row = row0 + r;
        int ok = (row < N) ? 16 : 0;
        const __half* ap = &A[(long long)row * K + k0 + h0];
        __half* dp = &As[(buf * 128 + r) * AS_LD + h0];
        cp16(dp,     ap,     ok);
        cp16(dp + 8, ap + 8, ok);
    };
    loadA(0, 0);
    cp_commit();

    float d[2][8][4];
#pragma unroll
    for (int i = 0; i < 2; ++i)
#pragma unroll
        for (int j = 0; j < 8; ++j)
#pragma unroll
            for (int p = 0; p < 4; ++p) d[i][j][p] = 0.f;

    const int r_ = lane >> 2;
    const int c_ = (lane & 3) * 2;
    constexpr int nt = K / 32;

#pragma unroll 1
    for (int t = 0; t < nt; ++t) {
        const int buf = t & 1;
        if (t + 1 < nt) { loadA(buf ^ 1, (t + 1) * 32); cp_commit(); cp_wait<1>(); }
        else            { cp_wait<0>(); }
        __syncthreads();
#pragma unroll
        for (int ks = 0; ks < 2; ++ks) {
            const int kk = ks * 16;
            unsigned a[2][4], b[8][2];
#pragma unroll
            for (int i = 0; i < 2; ++i) {
                const __half* base = &As[(buf * 128 + wm + i * 16 + r_) * AS_LD + kk + c_];
                a[i][0] = *(const unsigned*)base;
                a[i][1] = *(const unsigned*)(base + 8 * AS_LD);
                a[i][2] = *(const unsigned*)(base + 8);
                a[i][3] = *(const unsigned*)(base + 8 * AS_LD + 8);
            }
#pragma unroll
            for (int j = 0; j < 8; ++j) {
                const __half* bb = &Bs[(wn + j * 8 + r_) * BS_LD + t * 32 + kk + c_];
                b[j][0] = *(const unsigned*)bb;
                b[j][1] = *(const unsigned*)(bb + 8);
            }
#pragma unroll
            for (int i = 0; i < 2; ++i)
#pragma unroll
                for (int j = 0; j < 8; ++j)
                    mma16816(d[i][j], a[i], b[j]);
        }
        __syncthreads();
    }

#pragma unroll
    for (int i = 0; i < 2; ++i) {
#pragma unroll
        for (int hf = 0; hf < 2; ++hf) {
            int row = row0 + wm + i * 16 + hf * 8 + r_;
            if (row >= N) continue;
            float mult = 0.f;
            if (BIAS) mult = (float)(rowptr[row + 1] - rowptr[row]) + 1.0f;
#pragma unroll
            for (int j = 0; j < 8; ++j) {
                float v0 = d[i][j][hf * 2 + 0];
                float v1 = d[i][j][hf * 2 + 1];
                int col = wn + j * 8 + c_;
                if (BIAS) { v0 += mult * bias[col]; v1 += mult * bias[col + 1]; }
                if (RELU) { v0 = fmaxf(v0, 0.f); v1 = fmaxf(v1, 0.f); }
                if constexpr (sizeof(OutT) == 2) {
                    __half2 hv = __floats2half2_rn(v0, v1);
                    *(__half2*)((__half*)C + (long long)row * 128 + col) = hv;
                } else {
                    *(float2*)((float*)C + (long long)row * 128 + col) = make_float2(v0, v1);
                }
            }
        }
    }
}

// ========================= CSR gather-aggregate ============================
__device__ __forceinline__ float4 cvtP4(uint2 raw) {
    __half2 h0 = *(__half2*)&raw.x;
    __half2 h1 = *(__half2*)&raw.y;
    float2 f0 = __half22float2(h0);
    float2 f1 = __half22float2(h1);
    return make_float4(f0.x, f0.y, f1.x, f1.y);
}

__global__ __launch_bounds__(256)
void gather_kernel(const int* __restrict__ rowptr, const int* __restrict__ srcs,
                   const float2* __restrict__ eas,
                   const __half* __restrict__ P, __half* __restrict__ agg,
                   const float* __restrict__ w0, const float* __restrict__ w1,
                   const float* __restrict__ b, int N)
{
    const int lane = threadIdx.x & 31;
    const int c = lane * 4;
    const int warp = blockIdx.x * (blockDim.x >> 5) + (threadIdx.x >> 5);
    const int nwarps = gridDim.x * (blockDim.x >> 5);

    const float4 wa = *(const float4*)(w0 + c);
    const float4 wb = *(const float4*)(w1 + c);
    const float4 bb = *(const float4*)(b + c);

    for (int n = warp; n < N; n += nwarps) {
        const int s = rowptr[n];
        const int e = rowptr[n + 1];

        // self loop (ea = 1,1)
        float4 ps = cvtP4(*(const uint2*)(P + (long long)n * HD + c));
        float4 acc;
        acc.x = fmaxf(ps.x + wa.x + wb.x + bb.x, 0.f);
        acc.y = fmaxf(ps.y + wa.y + wb.y + bb.y, 0.f);
        acc.z = fmaxf(ps.z + wa.z + wb.z + bb.z, 0.f);
        acc.w = fmaxf(ps.w + wa.w + wb.w + bb.w, 0.f);

        int j = s;
        // 8-deep pipelined batches: all loads issued before any convert/acc
        for (; j + 8 <= e; j += 8) {
            uint2 raw[8];
            float2 ee[8];
#pragma unroll
            for (int q = 0; q < 8; ++q) {
                int sq = srcs[j + q];
                ee[q] = eas[j + q];
                raw[q] = *(const uint2*)(P + (long long)sq * HD + c);
            }
#pragma unroll
            for (int q = 0; q < 8; ++q) {
                float4 p = cvtP4(raw[q]);
                acc.x += fmaxf(fmaf(ee[q].x, wa.x, fmaf(ee[q].y, wb.x, p.x + bb.x)), 0.f);
                acc.y += fmaxf(fmaf(ee[q].x, wa.y, fmaf(ee[q].y, wb.y, p.y + bb.y)), 0.f);
                acc.z += fmaxf(fmaf(ee[q].x, wa.z, fmaf(ee[q].y, wb.z, p.z + bb.z)), 0.f);
                acc.w += fmaxf(fmaf(ee[q].x, wa.w, fmaf(ee[q].y, wb.w, p.w + bb.w)), 0.f);
            }
        }
        if (j + 4 <= e) {
            uint2 raw[4];
            float2 ee[4];
#pragma unroll
            for (int q = 0; q < 4; ++q) {
                int sq = srcs[j + q];
                ee[q] = eas[j + q];
                raw[q] = *(const uint2*)(P + (long long)sq * HD + c);
            }
#pragma unroll
            for (int q = 0; q < 4; ++q) {
                float4 p = cvtP4(raw[q]);
                acc.x += fmaxf(fmaf(ee[q].x, wa.x, fmaf(ee[q].y, wb.x, p.x + bb.x)), 0.f);
                acc.y += fmaxf(fmaf(ee[q].x, wa.y, fmaf(ee[q].y, wb.y, p.y + bb.y)), 0.f);
                acc.z += fmaxf(fmaf(ee[q].x, wa.z, fmaf(ee[q].y, wb.z, p.z + bb.z)), 0.f);
                acc.w += fmaxf(fmaf(ee[q].x, wa.w, fmaf(ee[q].y, wb.w, p.w + bb.w)), 0.f);
            }
            j += 4;
        }
        for (; j < e; ++j) {
            int sj = srcs[j];
            float2 ej = eas[j];
            float4 p = cvtP4(*(const uint2*)(P + (long long)sj * HD + c));
            acc.x += fmaxf(fmaf(ej.x, wa.x, fmaf(ej.y, wb.x, p.x + bb.x)), 0.f);
            acc.y += fmaxf(fmaf(ej.x, wa.y, fmaf(ej.y, wb.y, p.y + bb.y)), 0.f);
            acc.z += fmaxf(fmaf(ej.x, wa.z, fmaf(ej.y, wb.z, p.z + bb.z)), 0.f);
            acc.w += fmaxf(fmaf(ej.x, wa.w, fmaf(ej.y, wb.w, p.w + bb.w)), 0.f);
        }
        __half2 o0 = __floats2half2_rn(acc.x, acc.y);
        __half2 o1 = __floats2half2_rn(acc.z, acc.w);
        uint2 st;
        st.x = *(unsigned*)&o0;
        st.y = *(unsigned*)&o1;
        *(uint2*)(agg + (long long)n * HD + c) = st;
    }
}

// ---------------------------------------------------------------------------
extern "C" void kernel_launch(void* const* d_in, const int* in_sizes, int n_in,
                              void* d_out, int out_size)
{
    const float* x   = (const float*)d_in[0];
    const int*   ei  = (const int*)d_in[1];
    const float* ea  = (const float*)d_in[2];
    const float* W11 = (const float*)d_in[3];
    const float* b11 = (const float*)d_in[4];
    const float* W12 = (const float*)d_in[5];
    const float* b12 = (const float*)d_in[6];
    const float* W21 = (const float*)d_in[7];
    const float* b21 = (const float*)d_in[8];
    const float* W22 = (const float*)d_in[9];
    const float* b22 = (const float*)d_in[10];
    float* out = (float*)d_out;

    const int IN_DIM = 64;
    const int N = in_sizes[0] / IN_DIM;
    const int E = in_sizes[1] / 2;

    __half *P, *agg16, *h16, *x16, *wt11, *wt12, *wt21, *wt22;
    int *cnt, *fill, *rowptr, *bsum, *boff, *srcs;
    float2* eas;
    cudaGetSymbolAddress((void**)&P,      g_P);
    cudaGetSymbolAddress((void**)&agg16,  g_agg16);
    cudaGetSymbolAddress((void**)&h16,    g_h16);
    cudaGetSymbolAddress((void**)&x16,    g_x16);
    cudaGetSymbolAddress((void**)&wt11,   g_wt11);
    cudaGetSymbolAddress((void**)&wt12,   g_wt12);
    cudaGetSymbolAddress((void**)&wt21,   g_wt21);
    cudaGetSymbolAddress((void**)&wt22,   g_wt22);
    cudaGetSymbolAddress((void**)&cnt,    g_cnt);
    cudaGetSymbolAddress((void**)&fill,   g_fill);
    cudaGetSymbolAddress((void**)&rowptr, g_rowptr);
    cudaGetSymbolAddress((void**)&bsum,   g_bsum);
    cudaGetSymbolAddress((void**)&boff,   g_boff);
    cudaGetSymbolAddress((void**)&srcs,   g_src);
    cudaGetSymbolAddress((void**)&eas,    g_eas);

    const int gemm_blocks = (N + 127) / 128;
    const int gath_blocks = 148 * 16;
    const int nb = (N + 1023) / 1024;
    const int smem128 = (128 * (128 + 8) + 2 * 128 * 40) * 2;  // 55296 B
    const int smem64  = (128 * (64 + 8)  + 2 * 128 * 40) * 2;  // 38912 B

    static int attr_set = 0;
    if (!attr_set) {
        cudaFuncSetAttribute(hgemm_kernel<64,  __half, false, false>,
                             cudaFuncAttributeMaxDynamicSharedMemorySize, smem64);
        cudaFuncSetAttribute(hgemm_kernel<128, __half, true,  true>,
                             cudaFuncAttributeMaxDynamicSharedMemorySize, smem128);
        cudaFuncSetAttribute(hgemm_kernel<128, __half, false, false>,
                             cudaFuncAttributeMaxDynamicSharedMemorySize, smem128);
        cudaFuncSetAttribute(hgemm_kernel<128, float,  true,  false>,
                             cudaFuncAttributeMaxDynamicSharedMemorySize, smem128);
        attr_set = 1;
    }

    // ---- CSR build ----
    cudaMemsetAsync(cnt,  0, N * sizeof(int));
    cudaMemsetAsync(fill, 0, N * sizeof(int));
    count_kernel<<<(E + 255) / 256, 256>>>(ei, cnt, E);
    scan_reduce_kernel<<<nb, 256>>>(cnt, bsum, N);
    scan_bsums_kernel<<<1, 128>>>(bsum, boff, nb, rowptr, N, E);
    scan_block_kernel<<<nb, 1024>>>(cnt, boff, rowptr, N);
    fill_kernel<<<(E + 255) / 256, 256>>>(ei, ea, rowptr, fill, srcs, eas, E);

    // ---- conversions ----
    cvt_x_kernel<<<(N * 16 + 255) / 256, 256>>>(x, x16, N * 16);
    cvt_weights_kernel<<<(8192 + 49152 + 255) / 256, 256>>>(
        W11, W12, W21, W22, wt11, wt12, wt21, wt22);

    // ---- layer 1 ----
    hgemm_kernel<64, __half, false, false><<<gemm_blocks, 256, smem64>>>(
        x16, wt11, P, nullptr, nullptr, N);
    gather_kernel<<<gath_blocks, 256>>>(rowptr, srcs, eas, P, agg16,
                                        W11 + 64 * 128, W11 + 65 * 128, b11, N);
    hgemm_kernel<128, __half, true, true><<<gemm_blocks, 256, smem128>>>(
        agg16, wt12, h16, b12, rowptr, N);

    // ---- layer 2 ----
    hgemm_kernel<128, __half, false, false><<<gemm_blocks, 256, smem128>>>(
        h16, wt21, P, nullptr, nullptr, N);
    gather_kernel<<<gath_blocks, 256>>>(rowptr, srcs, eas, P, agg16,
                                        W21 + 128 * 128, W21 + 129 * 128, b21, N);
    hgemm_kernel<128, float, true, false><<<gemm_blocks, 256, smem128>>>(
        agg16, wt22, out, b22, rowptr, N);
}